// round 1
// baseline (speedup 1.0000x reference)
#include <cuda_runtime.h>

#define HW   196
#define NC   128
#define NB   8
#define CIN  512
#define NPIX 256
#define MM   16384          // NC*NC
#define EPSV 1e-11f

// ---------------- device scratch (static, no allocation) ----------------
__device__ float g_y  [NB * NC * NPIX];            // pointwise+relu  [b][c][256]
__device__ float g_xfT[NB * HW * NC];              // [b][p][c]
__device__ float g_xfN[NB * NC * HW];              // [b][c][p]
__device__ float g_R  [(size_t)NB * NC * NC * HW]; // logical [b][a][c][p]  ~98MB
__device__ float g_part[NB * 64];
__device__ float g_norm[NB];

// ---------------- Kernel A: y = relu(W @ x) per batch ----------------
// grid (4 pixTile, 4 oTile, 8 b), block 256 = 64 px * 4 og (8 o each)
__global__ void __launch_bounds__(256) pw_relu(const float* __restrict__ x,
                                               const float* __restrict__ w) {
    __shared__ float xs[32][64];
    __shared__ float ws[32][32];
    int b   = blockIdx.z;
    int o0  = blockIdx.y * 32;
    int px0 = blockIdx.x * 64;
    int tid = threadIdx.x;
    int px  = tid & 63;
    int og  = tid >> 6;

    float acc[8];
#pragma unroll
    for (int u = 0; u < 8; u++) acc[u] = 0.f;

    const float* xb = x + b * CIN * NPIX;
    for (int i0 = 0; i0 < CIN; i0 += 32) {
        __syncthreads();
#pragma unroll
        for (int r = 0; r < 8; r++) {            // 32*64 floats
            int idx = tid + r * 256;
            int i = idx >> 6, p = idx & 63;
            xs[i][p] = xb[(i0 + i) * NPIX + px0 + p];
        }
#pragma unroll
        for (int r = 0; r < 4; r++) {            // 32*32 floats
            int idx = tid + r * 256;
            int oo = idx >> 5, i = idx & 31;
            ws[oo][i] = w[(o0 + oo) * CIN + i0 + i];
        }
        __syncthreads();
#pragma unroll
        for (int i = 0; i < 32; i++) {
            float xv = xs[i][px];
#pragma unroll
            for (int u = 0; u < 8; u++)
                acc[u] = fmaf(ws[og * 8 + u][i], xv, acc[u]);
        }
    }
    float* yb = g_y + b * NC * NPIX;
#pragma unroll
    for (int u = 0; u < 8; u++)
        yb[(o0 + og * 8 + u) * NPIX + px0 + px] = fmaxf(acc[u], 0.f);
}

// ---------------- Kernel B: depthwise 3x3 gaussian, VALID ----------------
// grid (128 c, 8 b), block 256
__global__ void __launch_bounds__(256) dwconv() {
    __shared__ float s[256];
    int b = blockIdx.y, c = blockIdx.x;
    int t = threadIdx.x;
    s[t] = g_y[(b * NC + c) * NPIX + t];
    __syncthreads();
    if (t < HW) {
        const float G0 = 0.63661977f;   // 2/pi
        const float G1 = 0.08615711f;   // (2/pi) e^-2
        const float G2 = 0.01166010f;   // (2/pi) e^-4
        int oy = t / 14, ox = t - oy * 14;
        int r0 = oy * 16 + ox, r1 = r0 + 16, r2 = r0 + 32;
        float v = G2 * (s[r0] + s[r0 + 2] + s[r2] + s[r2 + 2])
                + G1 * (s[r0 + 1] + s[r1] + s[r1 + 2] + s[r2 + 1])
                + G0 * s[r1 + 1];
        g_xfT[(b * HW + t) * NC + c] = v;
        g_xfN[(b * NC + c) * HW + t] = v;
    }
}

// ---------------- Kernel C: circular correlation (the big one) ----------------
// R[b,a,c,p] = sum_i X[a,i] * X[c,(p-i) mod 196]
// grid (49 pTile, 4 = at*2+ct, 8 b), block 256, per-thread 4a x 4c x 4p
#define XA_SZ (HW * 64)       // [k][a]   12544
#define XB_RS 199             // odd stride -> conflict-free, +3 wrap cols
#define XB_SZ (64 * XB_RS)    // [c][j]   12736
__global__ void __launch_bounds__(256, 2) corr() {
    extern __shared__ float sm[];
    float* XA = sm;
    float* XB = sm + XA_SZ;

    int b  = blockIdx.z;
    int a0 = (blockIdx.y >> 1) * 64;
    int c0 = (blockIdx.y & 1) * 64;
    int p0 = blockIdx.x * 4;
    int tid = threadIdx.x;

    const float* xT = g_xfT + b * HW * NC;
    const float* xN = g_xfN + b * NC * HW;

    for (int idx = tid; idx < XA_SZ; idx += 256)
        XA[idx] = xT[(idx >> 6) * NC + a0 + (idx & 63)];
    for (int idx = tid; idx < XB_SZ; idx += 256) {
        int c = idx / XB_RS;
        int j = idx - c * XB_RS;
        int jj = (j < HW) ? j : j - HW;
        XB[idx] = xN[(c0 + c) * HW + jj];
    }
    __syncthreads();

    int tx = tid & 15, ty = tid >> 4;
    float acc[4][4][4];
#pragma unroll
    for (int ia = 0; ia < 4; ia++)
#pragma unroll
        for (int ic = 0; ic < 4; ic++)
#pragma unroll
            for (int ip = 0; ip < 4; ip++) acc[ia][ic][ip] = 0.f;

    int jb = p0;
#pragma unroll 2
    for (int k = 0; k < HW; k++) {
        float4 av = *(const float4*)(XA + k * 64 + ty * 4);
        float a4[4] = {av.x, av.y, av.z, av.w};
        float bv[4][4];
#pragma unroll
        for (int ic = 0; ic < 4; ic++) {
            const float* row = XB + (tx + ic * 16) * XB_RS + jb;
            bv[ic][0] = row[0];
            bv[ic][1] = row[1];
            bv[ic][2] = row[2];
            bv[ic][3] = row[3];
        }
#pragma unroll
        for (int ia = 0; ia < 4; ia++)
#pragma unroll
            for (int ic = 0; ic < 4; ic++)
#pragma unroll
                for (int ip = 0; ip < 4; ip++)
                    acc[ia][ic][ip] = fmaf(a4[ia], bv[ic][ip], acc[ia][ic][ip]);
        jb = (jb == 0) ? (HW - 1) : (jb - 1);
    }

    float* Rb = g_R + (size_t)b * (NC * NC * HW);
#pragma unroll
    for (int ia = 0; ia < 4; ia++) {
        int a = a0 + ty * 4 + ia;
#pragma unroll
        for (int ic = 0; ic < 4; ic++) {
            int c = c0 + tx + ic * 16;
            float4 o = make_float4(acc[ia][ic][0], acc[ia][ic][1],
                                   acc[ia][ic][2], acc[ia][ic][3]);
            *(float4*)(Rb + ((a * NC + c) * HW + p0)) = o;
        }
    }
}

// ---------------- Kernel D: max over q (flat stride 16384) + sqrt ----------------
// grid (64, 8 b), block 256 — fully coalesced reads of logical layout
__global__ void __launch_bounds__(256) maxred(float* __restrict__ out) {
    int b = blockIdx.y;
    int m = blockIdx.x * 256 + threadIdx.x;
    const float* Rb = g_R + (size_t)b * (NC * NC * HW);
    float m0 = -1e30f, m1 = -1e30f, m2 = -1e30f, m3 = -1e30f;
#pragma unroll 4
    for (int q = 0; q < HW; q += 4) {
        m0 = fmaxf(m0, Rb[(q + 0) * MM + m]);
        m1 = fmaxf(m1, Rb[(q + 1) * MM + m]);
        m2 = fmaxf(m2, Rb[(q + 2) * MM + m]);
        m3 = fmaxf(m3, Rb[(q + 3) * MM + m]);
    }
    float cij = sqrtf(fmaxf(fmaxf(m0, m1), fmaxf(m2, m3)));
    out[b * MM + m] = cij;

    // deterministic per-block partial sum of squares
    float v = cij * cij;
#pragma unroll
    for (int off = 16; off; off >>= 1) v += __shfl_down_sync(0xffffffffu, v, off);
    __shared__ float ssum[8];
    if ((threadIdx.x & 31) == 0) ssum[threadIdx.x >> 5] = v;
    __syncthreads();
    if (threadIdx.x == 0) {
        float s = 0.f;
#pragma unroll
        for (int i = 0; i < 8; i++) s += ssum[i];
        g_part[b * 64 + blockIdx.x] = s;
    }
}

// ---------------- Kernel N: reduce partials -> norm ----------------
__global__ void normk() {
    __shared__ float s[64];
    int b = blockIdx.x, t = threadIdx.x;
    s[t] = g_part[b * 64 + t];
    __syncthreads();
#pragma unroll
    for (int st = 32; st; st >>= 1) {
        if (t < st) s[t] += s[t + st];
        __syncthreads();
    }
    if (t == 0) g_norm[b] = s[0] + EPSV;
}

// ---------------- Kernel E: divide ----------------
__global__ void __launch_bounds__(256) divk(float* __restrict__ out) {
    int i = blockIdx.x * 256 + threadIdx.x;
    out[i] = out[i] / g_norm[i >> 14];
}

// ---------------- launch ----------------
extern "C" void kernel_launch(void* const* d_in, const int* in_sizes, int n_in,
                              void* d_out, int out_size) {
    const float* x = (const float*)d_in[0];
    const float* w = (const float*)d_in[1];
    if (in_sizes[0] == NC * CIN) {   // defensive: inputs swapped
        const float* t = x; x = w; w = t;
    }
    float* out = (float*)d_out;

    pw_relu<<<dim3(4, 4, NB), 256>>>(x, w);
    dwconv<<<dim3(NC, NB), 256>>>();

    size_t smem = (XA_SZ + XB_SZ) * sizeof(float);   // 101120 B
    cudaFuncSetAttribute(corr, cudaFuncAttributeMaxDynamicSharedMemorySize, (int)smem);
    corr<<<dim3(49, 4, NB), 256, smem>>>();

    maxred<<<dim3(64, NB), 256>>>(out);
    normk<<<NB, 64>>>();
    divk<<<512, 256>>>(out);
}

// round 2
// speedup vs baseline: 2.4582x; 2.4582x over previous
#include <cuda_runtime.h>
#include <cstdint>

#define HW   196
#define NC   128
#define NB   8
#define CIN  512
#define NPIX 256
#define MM   16384
#define EPSV 1e-11f

#define KPAD  208      // K padded to 13 k-steps of 16 (26 of 8)
#define XDW   416      // g_xd global row width (392 doubled + zero pad)
#define XR_ST 212      // smem stride for Xr (conflict-free for frag loads)
#define XD_ST 216      // smem Xd tile width (k<=207 + p_local<=7 + 1 + 4)

// ---------------- device scratch (zero-initialized .bss => pads stay 0) ---
__device__ float g_y  [NB * NC * NPIX];
__device__ float g_xr [NB * NC * KPAD];             // reversed rows, tf32-rounded
__device__ float g_xd [NB * NC * XDW];              // doubled rows,  tf32-rounded
__device__ float g_R  [(size_t)NB * NC * NC * HW];  // flat [b][a][c][p]
__device__ float g_part[NB * 64];
__device__ float g_norm[NB];

// ---------------- Kernel A: y = relu(W @ x) per batch --------------------
__global__ void __launch_bounds__(256) pw_relu(const float* __restrict__ x,
                                               const float* __restrict__ w) {
    __shared__ float xs[32][64];
    __shared__ float ws[32][32];
    int b   = blockIdx.z;
    int o0  = blockIdx.y * 32;
    int px0 = blockIdx.x * 64;
    int tid = threadIdx.x;
    int px  = tid & 63;
    int og  = tid >> 6;

    float acc[8];
#pragma unroll
    for (int u = 0; u < 8; u++) acc[u] = 0.f;

    const float* xb = x + b * CIN * NPIX;
    for (int i0 = 0; i0 < CIN; i0 += 32) {
        __syncthreads();
#pragma unroll
        for (int r = 0; r < 8; r++) {
            int idx = tid + r * 256;
            int i = idx >> 6, p = idx & 63;
            xs[i][p] = xb[(i0 + i) * NPIX + px0 + p];
        }
#pragma unroll
        for (int r = 0; r < 4; r++) {
            int idx = tid + r * 256;
            int oo = idx >> 5, i = idx & 31;
            ws[oo][i] = w[(o0 + oo) * CIN + i0 + i];
        }
        __syncthreads();
#pragma unroll
        for (int i = 0; i < 32; i++) {
            float xv = xs[i][px];
#pragma unroll
            for (int u = 0; u < 8; u++)
                acc[u] = fmaf(ws[og * 8 + u][i], xv, acc[u]);
        }
    }
    float* yb = g_y + b * NC * NPIX;
#pragma unroll
    for (int u = 0; u < 8; u++)
        yb[(o0 + og * 8 + u) * NPIX + px0 + px] = fmaxf(acc[u], 0.f);
}

// ---------------- Kernel B: depthwise 3x3 gaussian + tf32 prep -----------
// writes Xr (reversed, zero-padded) and Xd (doubled) rows, tf32-rounded
__global__ void __launch_bounds__(256) prep() {
    __shared__ float s[256];
    int b = blockIdx.y, c = blockIdx.x;
    int t = threadIdx.x;
    s[t] = g_y[(b * NC + c) * NPIX + t];
    __syncthreads();
    if (t < HW) {
        const float G0 = 0.63661977f;
        const float G1 = 0.08615711f;
        const float G2 = 0.01166010f;
        int oy = t / 14, ox = t - oy * 14;
        int r0 = oy * 16 + ox, r1 = r0 + 16, r2 = r0 + 32;
        float v = G2 * (s[r0] + s[r0 + 2] + s[r2] + s[r2 + 2])
                + G1 * (s[r0 + 1] + s[r1] + s[r1 + 2] + s[r2 + 1])
                + G0 * s[r1 + 1];
        uint32_t tv;
        asm("cvt.rna.tf32.f32 %0, %1;" : "=r"(tv) : "f"(v));
        float vt = __uint_as_float(tv);
        g_xr[(b * NC + c) * KPAD + (195 - t)] = vt;
        float* xd = g_xd + (b * NC + c) * XDW;
        xd[t]      = vt;
        xd[t + HW] = vt;
    }
}

// ---------------- Kernel C: correlation via tf32 mma.sync ----------------
// R[a,c,p] = sum_k Xr[a,k] * Xd[c, k+p+1]
// CTA tile: M=64 (a) x N=256 (32 c x 8 p). 8 warps = 2 (m) x 4 (n).
// Warp tile: 32m x 64n (2 m-tiles of 16, 8 n-tiles of 8; each n-tile = 1 c x 8 p)
__global__ void __launch_bounds__(256, 2) corr_tc() {
    extern __shared__ float sm[];
    float* Xr_s = sm;                    // [64][XR_ST]
    float* Xd_s = sm + 64 * XR_ST;       // [32][XD_ST]

    int b  = blockIdx.z;
    int c0 = blockIdx.y * 32;
    int pt = blockIdx.x % 25;
    int at = blockIdx.x / 25;
    int a0 = at * 64;
    int p0 = pt * 8;
    int tid = threadIdx.x;

    // stage A: 64 rows x 208 = 3328 float4
    for (int i = tid; i < 3328; i += 256) {
        int r = i / 52, q = i - r * 52;
        float4 v = *(const float4*)(g_xr + ((b * NC + a0 + r) * KPAD) + q * 4);
        *(float4*)(Xr_s + r * XR_ST + q * 4) = v;
    }
    // stage B source: 32 rows x 216 floats starting at column p0 (float4-aligned)
    for (int i = tid; i < 1728; i += 256) {
        int r = i / 54, q = i - r * 54;
        float4 v = *(const float4*)(g_xd + ((b * NC + c0 + r) * XDW) + p0 + q * 4);
        *(float4*)(Xd_s + r * XD_ST + q * 4) = v;
    }
    __syncthreads();

    int lane = tid & 31, w = tid >> 5;
    int wm = w >> 2, wn = w & 3;       // wm 0..1 (m), wn 0..3 (n)
    int lr = lane >> 2, lk = lane & 3;

    float acc[2][8][4];
#pragma unroll
    for (int mi = 0; mi < 2; mi++)
#pragma unroll
        for (int nt = 0; nt < 8; nt++)
#pragma unroll
            for (int u = 0; u < 4; u++) acc[mi][nt][u] = 0.f;

    const float* aP = Xr_s + (wm * 32 + lr) * XR_ST + lk;
    const float* bP = Xd_s + (wn * 8) * XD_ST + (lk + lr + 1);

#pragma unroll 2
    for (int k0 = 0; k0 < KPAD; k0 += 8) {
        uint32_t afr[2][4];
#pragma unroll
        for (int mi = 0; mi < 2; mi++) {
            const float* ap = aP + mi * 16 * XR_ST + k0;
            afr[mi][0] = __float_as_uint(ap[0]);
            afr[mi][1] = __float_as_uint(ap[8 * XR_ST]);
            afr[mi][2] = __float_as_uint(ap[4]);
            afr[mi][3] = __float_as_uint(ap[8 * XR_ST + 4]);
        }
#pragma unroll
        for (int nt = 0; nt < 8; nt++) {
            const float* bp = bP + nt * XD_ST + k0;
            uint32_t b0 = __float_as_uint(bp[0]);
            uint32_t b1 = __float_as_uint(bp[4]);
#pragma unroll
            for (int mi = 0; mi < 2; mi++) {
                asm volatile(
                    "mma.sync.aligned.m16n8k8.row.col.f32.tf32.tf32.f32 "
                    "{%0,%1,%2,%3}, {%4,%5,%6,%7}, {%8,%9}, {%0,%1,%2,%3};"
                    : "+f"(acc[mi][nt][0]), "+f"(acc[mi][nt][1]),
                      "+f"(acc[mi][nt][2]), "+f"(acc[mi][nt][3])
                    : "r"(afr[mi][0]), "r"(afr[mi][1]),
                      "r"(afr[mi][2]), "r"(afr[mi][3]),
                      "r"(b0), "r"(b1));
            }
        }
    }

    // epilogue: D[m][n] -> R[a][c][p], n-tile = one c x 8 p
    float* Rb = g_R + (size_t)b * (NC * NC * HW);
    int pe = p0 + lk * 2;
    if (pe < HW) {
#pragma unroll
        for (int mi = 0; mi < 2; mi++) {
            int ar = a0 + wm * 32 + mi * 16 + lr;
#pragma unroll
            for (int nt = 0; nt < 8; nt++) {
                int c = c0 + wn * 8 + nt;
                *(float2*)(Rb + ((ar * NC + c) * HW + pe)) =
                    make_float2(acc[mi][nt][0], acc[mi][nt][1]);
                *(float2*)(Rb + (((ar + 8) * NC + c) * HW + pe)) =
                    make_float2(acc[mi][nt][2], acc[mi][nt][3]);
            }
        }
    }
}

// ---------------- Kernel D: max over q + sqrt + partial norms ------------
__global__ void __launch_bounds__(256) maxred(float* __restrict__ out) {
    int b = blockIdx.y;
    int m = blockIdx.x * 256 + threadIdx.x;
    const float* Rb = g_R + (size_t)b * (NC * NC * HW);
    float mx[8];
#pragma unroll
    for (int u = 0; u < 8; u++) mx[u] = 0.f;   // R >= 0
#pragma unroll 3
    for (int q = 0; q < 192; q += 8) {
#pragma unroll
        for (int u = 0; u < 8; u++)
            mx[u] = fmaxf(mx[u], Rb[(size_t)(q + u) * MM + m]);
    }
#pragma unroll
    for (int u = 0; u < 4; u++)
        mx[u] = fmaxf(mx[u], Rb[(size_t)(192 + u) * MM + m]);
#pragma unroll
    for (int s = 4; s; s >>= 1)
#pragma unroll
        for (int u = 0; u < s; u++) mx[u] = fmaxf(mx[u], mx[u + s]);
    float cij = sqrtf(mx[0]);
    out[b * MM + m] = cij;

    float v = cij * cij;
#pragma unroll
    for (int off = 16; off; off >>= 1) v += __shfl_down_sync(0xffffffffu, v, off);
    __shared__ float ssum[8];
    if ((threadIdx.x & 31) == 0) ssum[threadIdx.x >> 5] = v;
    __syncthreads();
    if (threadIdx.x == 0) {
        float s = 0.f;
#pragma unroll
        for (int i = 0; i < 8; i++) s += ssum[i];
        g_part[b * 64 + blockIdx.x] = s;
    }
}

// ---------------- Kernel N: reduce partials -> norm -----------------------
__global__ void normk() {
    __shared__ float s[64];
    int b = blockIdx.x, t = threadIdx.x;
    s[t] = g_part[b * 64 + t];
    __syncthreads();
#pragma unroll
    for (int st = 32; st; st >>= 1) {
        if (t < st) s[t] += s[t + st];
        __syncthreads();
    }
    if (t == 0) g_norm[b] = s[0] + EPSV;
}

// ---------------- Kernel E: divide ----------------------------------------
__global__ void __launch_bounds__(256) divk(float* __restrict__ out) {
    int i = blockIdx.x * 256 + threadIdx.x;
    out[i] = out[i] / g_norm[i >> 14];
}

// ---------------- launch ---------------------------------------------------
extern "C" void kernel_launch(void* const* d_in, const int* in_sizes, int n_in,
                              void* d_out, int out_size) {
    const float* x = (const float*)d_in[0];
    const float* w = (const float*)d_in[1];
    if (in_sizes[0] == NC * CIN) {
        const float* t = x; x = w; w = t;
    }
    float* out = (float*)d_out;

    pw_relu<<<dim3(4, 4, NB), 256>>>(x, w);
    prep<<<dim3(NC, NB), 256>>>();

    size_t smem = (64 * XR_ST + 32 * XD_ST) * sizeof(float);   // 81920
    cudaFuncSetAttribute(corr_tc, cudaFuncAttributeMaxDynamicSharedMemorySize,
                         (int)smem);
    corr_tc<<<dim3(50, 4, NB), 256, smem>>>();

    maxred<<<dim3(64, NB), 256>>>(out);
    normk<<<NB, 64>>>();
    divk<<<512, 256>>>(out);
}

// round 5
// speedup vs baseline: 3.8442x; 1.5638x over previous
#include <cuda_runtime.h>
#include <cuda_fp16.h>
#include <cstdint>

#define HW   196
#define NC   128
#define NB   8
#define CIN  512
#define NPIX 256
#define MM   16384
#define EPSV 1e-11f
#define KPAD 208            // K padded to 13 k-steps of 16
#define XDW  424            // global doubled-row width (halfs, 16B-mult)
#define XRS  232            // Xr smem row stride (halfs)
#define XDS  224            // Xd smem row width (halfs)
#define WSZ  802816         // 4096*196 = 49*16384

// ---------------- device scratch (.bss zero-init) --------------------------
__device__ float  g_y   [NB * NC * NPIX];
__device__ __half g_xrh [NB * NC * KPAD];   // reversed rows, fp16, zero pad
__device__ __half g_xdh [NB * NC * XDW];    // xd[j]  = X[j mod 196], j<=423
__device__ __half g_xdh1[NB * NC * XDW];    // x1[j]  = X[(j+1) mod 196]
__device__ float  g_W   [(size_t)NB * WSZ]; // [b][f], f=(a32*128+c)*196+p
__device__ float  g_part[NB * 64];
__device__ float  g_norm[NB];

// ---------------- Kernel A: y = relu(W @ x) --------------------------------
__global__ void __launch_bounds__(256) pw_relu(const float* __restrict__ x,
                                               const float* __restrict__ w) {
    __shared__ float xs[32][64];
    __shared__ float ws[32][32];
    int b = blockIdx.z, o0 = blockIdx.y * 32, px0 = blockIdx.x * 64;
    int tid = threadIdx.x, px = tid & 63, og = tid >> 6;
    float acc[8];
#pragma unroll
    for (int u = 0; u < 8; u++) acc[u] = 0.f;
    const float* xb = x + b * CIN * NPIX;
    for (int i0 = 0; i0 < CIN; i0 += 32) {
        __syncthreads();
#pragma unroll
        for (int r = 0; r < 8; r++) {
            int idx = tid + r * 256;
            xs[idx >> 6][idx & 63] = xb[(i0 + (idx >> 6)) * NPIX + px0 + (idx & 63)];
        }
#pragma unroll
        for (int r = 0; r < 4; r++) {
            int idx = tid + r * 256;
            ws[idx >> 5][idx & 31] = w[(o0 + (idx >> 5)) * CIN + i0 + (idx & 31)];
        }
        __syncthreads();
#pragma unroll
        for (int i = 0; i < 32; i++) {
            float xv = xs[i][px];
#pragma unroll
            for (int u = 0; u < 8; u++)
                acc[u] = fmaf(ws[og * 8 + u][i], xv, acc[u]);
        }
    }
    float* yb = g_y + b * NC * NPIX;
#pragma unroll
    for (int u = 0; u < 8; u++)
        yb[(o0 + og * 8 + u) * NPIX + px0 + px] = fmaxf(acc[u], 0.f);
}

// ---------------- Kernel B: gaussian conv + fp16 prep ----------------------
__global__ void __launch_bounds__(256) prep() {
    __shared__ float s[256];
    int b = blockIdx.y, c = blockIdx.x, t = threadIdx.x;
    s[t] = g_y[(b * NC + c) * NPIX + t];
    __syncthreads();
    if (t < HW) {
        const float G0 = 0.63661977f, G1 = 0.08615711f, G2 = 0.01166010f;
        int oy = t / 14, ox = t - oy * 14;
        int r0 = oy * 16 + ox, r1 = r0 + 16, r2 = r0 + 32;
        float v = G2 * (s[r0] + s[r0 + 2] + s[r2] + s[r2 + 2])
                + G1 * (s[r0 + 1] + s[r1] + s[r1 + 2] + s[r2 + 1])
                + G0 * s[r1 + 1];
        __half h = __float2half_rn(v);
        g_xrh[(b * NC + c) * KPAD + (195 - t)] = h;
        __half* xd = g_xdh + (size_t)(b * NC + c) * XDW;
        xd[t]      = h;              // j = t
        xd[t + HW] = h;              // j = t + 196
        if (t < 32) xd[t + 392] = h; // j = t + 392  (covers window tail)
        __half* x1 = g_xdh1 + (size_t)(b * NC + c) * XDW;
        x1[t + 195] = h;             // j = t + 195 -> X[(j+1)%196] = X[t]
        if (t) x1[t - 1] = h;        // j = t - 1
        if (t < 33) x1[t + 391] = h; // j = t + 391 -> X[(t+392)%196] = X[t]
    }
}

// ---------------- Kernel C: fp16 mma correlation + fused 4-group max -------
// CTA: M=128 (all a) x N=128 (16 c x 8 p), K=208. grid (25 pt, 8 ct, 8 b).
// 8 warps = 2 (wm over a-halves) x 4 (wn over n). Warp tile 64m x 32n.
__global__ void __launch_bounds__(256, 2) corr6() {
    extern __shared__ char dyn[];
    __half* XrS = (__half*)dyn;                         // [128][XRS]
    __half* XdA = (__half*)(dyn + 128 * XRS * 2);       // [16][XDS]
    __half* XdB = XdA + 16 * XDS + 16;                  // [16][XDS], +16 bank shift
    float*  sbuf = (float*)dyn;                         // epilogue overlay (16KB)

    int b  = blockIdx.z;
    int c0 = blockIdx.y * 16;
    int p0 = blockIdx.x * 8;
    int tid = threadIdx.x;

    // stage Xr: 128 rows x 26 int4
    {
        const int4* xr = (const int4*)(g_xrh + (size_t)b * NC * KPAD);
        for (int i = tid; i < 3328; i += 256) {
            int r = i / 26, q = i - r * 26;
            *(int4*)(XrS + r * XRS + q * 8) = xr[r * 26 + q];
        }
    }
    // stage XdA (window at p0, unshifted) and XdB (window at p0, +1 shifted)
    for (int i = tid; i < 896; i += 256) {
        int sel = (i >= 448);
        int ii = sel ? (i - 448) : i;          // FIXED (was i & 447)
        int r = ii / 28, q = ii - r * 28;
        const __half* src = (sel ? g_xdh1 : g_xdh)
                          + (size_t)(b * NC + c0 + r) * XDW + p0 + q * 8;
        __half* dst = (sel ? XdB : XdA) + r * XDS + q * 8;
        *(int4*)dst = *(const int4*)src;
    }
    __syncthreads();

    int lane = tid & 31, w = tid >> 5;
    int wm = w >> 2, wn = w & 3;
    int lr = lane >> 2, lk = lane & 3;

    const __half* arow[4];
#pragma unroll
    for (int mi = 0; mi < 4; mi++)
        arow[mi] = XrS + (wm * 64 + mi * 16 + lr) * XRS + lk * 2;

    // B fragment: n (=lane/4=lr) is p_local; parity-select copy for alignment
    const __half* brow[4];
    {
        const __half* pb = (lr & 1) ? (XdA + lr + 1) : (XdB + lr);
#pragma unroll
        for (int nt = 0; nt < 4; nt++)
            brow[nt] = pb + (wn * 4 + nt) * XDS + lk * 2;
    }

    float acc[4][4][4];
#pragma unroll
    for (int mi = 0; mi < 4; mi++)
#pragma unroll
        for (int nt = 0; nt < 4; nt++)
#pragma unroll
            for (int u = 0; u < 4; u++) acc[mi][nt][u] = 0.f;

#pragma unroll
    for (int k = 0; k < KPAD; k += 16) {
        uint32_t af[4][4];
#pragma unroll
        for (int mi = 0; mi < 4; mi++) {
            af[mi][0] = *(const uint32_t*)(arow[mi] + k);
            af[mi][1] = *(const uint32_t*)(arow[mi] + 8 * XRS + k);
            af[mi][2] = *(const uint32_t*)(arow[mi] + k + 8);
            af[mi][3] = *(const uint32_t*)(arow[mi] + 8 * XRS + k + 8);
        }
#pragma unroll
        for (int nt = 0; nt < 4; nt++) {
            uint32_t b0 = *(const uint32_t*)(brow[nt] + k);
            uint32_t b1 = *(const uint32_t*)(brow[nt] + k + 8);
#pragma unroll
            for (int mi = 0; mi < 4; mi++) {
                asm volatile(
                    "mma.sync.aligned.m16n8k16.row.col.f32.f16.f16.f32 "
                    "{%0,%1,%2,%3},{%4,%5,%6,%7},{%8,%9},{%0,%1,%2,%3};"
                    : "+f"(acc[mi][nt][0]), "+f"(acc[mi][nt][1]),
                      "+f"(acc[mi][nt][2]), "+f"(acc[mi][nt][3])
                    : "r"(af[mi][0]), "r"(af[mi][1]),
                      "r"(af[mi][2]), "r"(af[mi][3]),
                      "r"(b0), "r"(b1));
            }
        }
    }

    // in-warp group max: a and a+32  (mi j vs j+2)
    float red[2][4][4];
#pragma unroll
    for (int j = 0; j < 2; j++)
#pragma unroll
        for (int nt = 0; nt < 4; nt++)
#pragma unroll
            for (int u = 0; u < 4; u++)
                red[j][nt][u] = fmaxf(acc[j][nt][u], acc[j + 2][nt][u]);

    __syncthreads();   // operands consumed; overlay sbuf
    if (wm == 1) {
#pragma unroll
        for (int j = 0; j < 2; j++)
#pragma unroll
            for (int nt = 0; nt < 4; nt++)
#pragma unroll
                for (int u = 0; u < 4; u++)
                    sbuf[wn * 1024 + ((j * 4 + nt) * 4 + u) * 32 + lane] =
                        red[j][nt][u];
    }
    __syncthreads();
    if (wm == 0) {
        int pe = p0 + lk * 2;
        float* Wb = g_W + (size_t)b * WSZ;
#pragma unroll
        for (int j = 0; j < 2; j++)
#pragma unroll
            for (int nt = 0; nt < 4; nt++) {
                float v0 = fmaxf(red[j][nt][0],
                                 sbuf[wn * 1024 + ((j * 4 + nt) * 4 + 0) * 32 + lane]);
                float v1 = fmaxf(red[j][nt][1],
                                 sbuf[wn * 1024 + ((j * 4 + nt) * 4 + 1) * 32 + lane]);
                float v2 = fmaxf(red[j][nt][2],
                                 sbuf[wn * 1024 + ((j * 4 + nt) * 4 + 2) * 32 + lane]);
                float v3 = fmaxf(red[j][nt][3],
                                 sbuf[wn * 1024 + ((j * 4 + nt) * 4 + 3) * 32 + lane]);
                if (pe < HW) {
                    int c  = c0 + wn * 4 + nt;
                    int s0 = (j * 16 + lr) * 128 + c;
                    *(float2*)(Wb + (size_t)s0 * HW + pe) = make_float2(v0, v1);
                    *(float2*)(Wb + (size_t)(s0 + 1024) * HW + pe) = make_float2(v2, v3);
                }
            }
    }
}

// ---------------- Kernel D: max over 49 strided rows + sqrt + norm ---------
__global__ void __launch_bounds__(256) maxred2(float* __restrict__ out) {
    int b = blockIdx.y;
    int m = blockIdx.x * 256 + threadIdx.x;
    const float* Wb = g_W + (size_t)b * WSZ;
    float m0 = 0.f, m1 = 0.f, m2 = 0.f, m3 = 0.f;
#pragma unroll 3
    for (int j = 0; j < 48; j += 4) {
        m0 = fmaxf(m0, Wb[(size_t)(j + 0) * MM + m]);
        m1 = fmaxf(m1, Wb[(size_t)(j + 1) * MM + m]);
        m2 = fmaxf(m2, Wb[(size_t)(j + 2) * MM + m]);
        m3 = fmaxf(m3, Wb[(size_t)(j + 3) * MM + m]);
    }
    m0 = fmaxf(m0, Wb[(size_t)48 * MM + m]);
    float cij = sqrtf(fmaxf(fmaxf(m0, m1), fmaxf(m2, m3)));
    out[b * MM + m] = cij;

    float v = cij * cij;
#pragma unroll
    for (int off = 16; off; off >>= 1) v += __shfl_down_sync(0xffffffffu, v, off);
    __shared__ float ssum[8];
    if ((threadIdx.x & 31) == 0) ssum[threadIdx.x >> 5] = v;
    __syncthreads();
    if (threadIdx.x == 0) {
        float s = 0.f;
#pragma unroll
        for (int i = 0; i < 8; i++) s += ssum[i];
        g_part[b * 64 + blockIdx.x] = s;
    }
}

__global__ void normk() {
    __shared__ float s[64];
    int b = blockIdx.x, t = threadIdx.x;
    s[t] = g_part[b * 64 + t];
    __syncthreads();
#pragma unroll
    for (int st = 32; st; st >>= 1) {
        if (t < st) s[t] += s[t + st];
        __syncthreads();
    }
    if (t == 0) g_norm[b] = s[0] + EPSV;
}

__global__ void __launch_bounds__(256) divk(float* __restrict__ out) {
    int i = blockIdx.x * 256 + threadIdx.x;
    out[i] = out[i] / g_norm[i >> 14];
}

// ---------------- launch ----------------------------------------------------
extern "C" void kernel_launch(void* const* d_in, const int* in_sizes, int n_in,
                              void* d_out, int out_size) {
    const float* x = (const float*)d_in[0];
    const float* w = (const float*)d_in[1];
    if (in_sizes[0] == NC * CIN) { const float* t = x; x = w; w = t; }
    float* out = (float*)d_out;

    pw_relu<<<dim3(4, 4, NB), 256>>>(x, w);
    prep<<<dim3(NC, NB), 256>>>();

    int smem = (128 * XRS + 2 * 16 * XDS + 16) * 2;   // 73760 bytes
    cudaFuncSetAttribute(corr6, cudaFuncAttributeMaxDynamicSharedMemorySize, smem);
    corr6<<<dim3(25, 8, NB), 256, smem>>>();

    maxred2<<<dim3(64, NB), 256>>>(out);
    normk<<<NB, 64>>>();
    divk<<<512, 256>>>(out);
}

// round 6
// speedup vs baseline: 3.9079x; 1.0165x over previous
#include <cuda_runtime.h>
#include <cuda_fp16.h>
#include <cstdint>

#define HW   196
#define NC   128
#define NB   8
#define CIN  512
#define NPIX 256
#define MM   16384
#define EPSV 1e-11f
#define KPAD 208            // K padded to 13 k-steps of 16
#define XDW  424            // global doubled-row width (halfs, 16B-mult)
#define XRS  232            // Xr smem row stride (halfs)
#define XDS  224            // Xd smem row width (halfs)
#define WSZ  802816         // 4096*196 = 49*16384

// ---------------- device scratch (.bss zero-init) --------------------------
__device__ float  g_yp  [4][NB * NC * NPIX];  // K-split partials
__device__ __half g_xrh [NB * NC * KPAD];     // reversed rows, fp16, zero pad
__device__ __half g_xdh [NB * NC * XDW];      // xd[j] = X[j mod 196]
__device__ __half g_xdh1[NB * NC * XDW];      // x1[j] = X[(j+1) mod 196]
__device__ float  g_W   [(size_t)NB * WSZ];   // [b][f], f=(a32*128+c)*196+p
__device__ float  g_part[NB * 64];
__device__ float  g_norm[NB];

// ---------------- Kernel A: partial y = W @ x (K-split by 4) ---------------
__global__ void __launch_bounds__(256) pw4(const float* __restrict__ x,
                                           const float* __restrict__ w) {
    __shared__ float xs[32][64];
    __shared__ float ws[32][32];
    int bz = blockIdx.z, b = bz >> 2, ks = bz & 3;
    int o0 = blockIdx.y * 32, px0 = blockIdx.x * 64;
    int tid = threadIdx.x, px = tid & 63, og = tid >> 6;
    float acc[8];
#pragma unroll
    for (int u = 0; u < 8; u++) acc[u] = 0.f;
    const float* xb = x + b * CIN * NPIX;
    int ibase = ks * 128;
    for (int i0 = ibase; i0 < ibase + 128; i0 += 32) {
        __syncthreads();
#pragma unroll
        for (int r = 0; r < 8; r++) {
            int idx = tid + r * 256;
            xs[idx >> 6][idx & 63] = xb[(i0 + (idx >> 6)) * NPIX + px0 + (idx & 63)];
        }
#pragma unroll
        for (int r = 0; r < 4; r++) {
            int idx = tid + r * 256;
            ws[idx >> 5][idx & 31] = w[(o0 + (idx >> 5)) * CIN + i0 + (idx & 31)];
        }
        __syncthreads();
#pragma unroll
        for (int i = 0; i < 32; i++) {
            float xv = xs[i][px];
#pragma unroll
            for (int u = 0; u < 8; u++)
                acc[u] = fmaf(ws[og * 8 + u][i], xv, acc[u]);
        }
    }
    float* yb = g_yp[ks] + b * NC * NPIX;
#pragma unroll
    for (int u = 0; u < 8; u++)
        yb[(o0 + og * 8 + u) * NPIX + px0 + px] = acc[u];
}

// ---------------- Kernel B: sum partials + relu + gaussian + fp16 prep -----
__global__ void __launch_bounds__(256) prep() {
    __shared__ float s[256];
    int b = blockIdx.y, c = blockIdx.x, t = threadIdx.x;
    int off = (b * NC + c) * NPIX + t;
    s[t] = fmaxf(g_yp[0][off] + g_yp[1][off] + g_yp[2][off] + g_yp[3][off], 0.f);
    __syncthreads();
    if (t < HW) {
        const float G0 = 0.63661977f, G1 = 0.08615711f, G2 = 0.01166010f;
        int oy = t / 14, ox = t - oy * 14;
        int r0 = oy * 16 + ox, r1 = r0 + 16, r2 = r0 + 32;
        float v = G2 * (s[r0] + s[r0 + 2] + s[r2] + s[r2 + 2])
                + G1 * (s[r0 + 1] + s[r1] + s[r1 + 2] + s[r2 + 1])
                + G0 * s[r1 + 1];
        __half h = __float2half_rn(v);
        g_xrh[(b * NC + c) * KPAD + (195 - t)] = h;
        __half* xd = g_xdh + (size_t)(b * NC + c) * XDW;
        xd[t]      = h;
        xd[t + HW] = h;
        if (t < 32) xd[t + 392] = h;
        __half* x1 = g_xdh1 + (size_t)(b * NC + c) * XDW;
        x1[t + 195] = h;
        if (t) x1[t - 1] = h;
        if (t < 33) x1[t + 391] = h;
    }
}

__device__ __forceinline__ uint32_t smem_u32(const void* p) {
    uint32_t a;
    asm("{ .reg .u64 t; cvta.to.shared.u64 t, %1; cvt.u32.u64 %0, t; }"
        : "=r"(a) : "l"(p));
    return a;
}

// ---------------- Kernel C: fp16 mma correlation + fused 4-group max -------
// CTA: M=128 (all a) x N=128 (16 c x 8 p), K=208. grid (25 pt, 8 ct, 8 b).
__global__ void __launch_bounds__(256, 2) corr6() {
    extern __shared__ char dyn[];
    __half* XrS = (__half*)dyn;                         // [128][XRS]
    __half* XdA = (__half*)(dyn + 128 * XRS * 2);       // [16][XDS]
    __half* XdB = XdA + 16 * XDS + 16;                  // [16][XDS], bank shift
    float*  sbuf = (float*)dyn;                         // epilogue overlay

    int b  = blockIdx.z;
    int c0 = blockIdx.y * 16;
    int p0 = blockIdx.x * 8;
    int tid = threadIdx.x;

    // stage Xr: 128 rows x 26 int4
    {
        const int4* xr = (const int4*)(g_xrh + (size_t)b * NC * KPAD);
        for (int i = tid; i < 3328; i += 256) {
            int r = i / 26, q = i - r * 26;
            *(int4*)(XrS + r * XRS + q * 8) = xr[r * 26 + q];
        }
    }
    // stage XdA (window, unshifted) and XdB (window, +1 shifted)
    for (int i = tid; i < 896; i += 256) {
        int sel = (i >= 448);
        int ii = sel ? (i - 448) : i;
        int r = ii / 28, q = ii - r * 28;
        const __half* src = (sel ? g_xdh1 : g_xdh)
                          + (size_t)(b * NC + c0 + r) * XDW + p0 + q * 8;
        __half* dst = (sel ? XdB : XdA) + r * XDS + q * 8;
        *(int4*)dst = *(const int4*)src;
    }
    __syncthreads();

    int lane = tid & 31, w = tid >> 5;
    int wm = w >> 2, wn = w & 3;
    int lr = lane >> 2, lk = lane & 3;

    // ldmatrix.x4 base addresses for the 4 m-tiles
    uint32_t a_addr[4];
    {
        int arow = wm * 64 + (lane & 7) + ((lane >> 3) & 1) * 8;
        int acol = (lane >> 4) * 8;
        uint32_t base = smem_u32(XrS);
#pragma unroll
        for (int mi = 0; mi < 4; mi++)
            a_addr[mi] = base + (uint32_t)(((arow + mi * 16) * XRS + acol) * 2);
    }

    const __half* brow[4];
    {
        const __half* pb = (lr & 1) ? (XdA + lr + 1) : (XdB + lr);
#pragma unroll
        for (int nt = 0; nt < 4; nt++)
            brow[nt] = pb + (wn * 4 + nt) * XDS + lk * 2;
    }

    float acc[4][4][4];
#pragma unroll
    for (int mi = 0; mi < 4; mi++)
#pragma unroll
        for (int nt = 0; nt < 4; nt++)
#pragma unroll
            for (int u = 0; u < 4; u++) acc[mi][nt][u] = 0.f;

#pragma unroll
    for (int k = 0; k < KPAD; k += 16) {
        uint32_t af[4][4];
#pragma unroll
        for (int mi = 0; mi < 4; mi++) {
            asm volatile(
                "ldmatrix.sync.aligned.m8n8.x4.shared.b16 {%0,%1,%2,%3}, [%4];"
                : "=r"(af[mi][0]), "=r"(af[mi][1]),
                  "=r"(af[mi][2]), "=r"(af[mi][3])
                : "r"(a_addr[mi] + (uint32_t)(k * 2)));
        }
#pragma unroll
        for (int nt = 0; nt < 4; nt++) {
            uint32_t b0 = *(const uint32_t*)(brow[nt] + k);
            uint32_t b1 = *(const uint32_t*)(brow[nt] + k + 8);
#pragma unroll
            for (int mi = 0; mi < 4; mi++) {
                asm volatile(
                    "mma.sync.aligned.m16n8k16.row.col.f32.f16.f16.f32 "
                    "{%0,%1,%2,%3},{%4,%5,%6,%7},{%8,%9},{%0,%1,%2,%3};"
                    : "+f"(acc[mi][nt][0]), "+f"(acc[mi][nt][1]),
                      "+f"(acc[mi][nt][2]), "+f"(acc[mi][nt][3])
                    : "r"(af[mi][0]), "r"(af[mi][1]),
                      "r"(af[mi][2]), "r"(af[mi][3]),
                      "r"(b0), "r"(b1));
            }
        }
    }

    // in-warp group max: a and a+32
    float red[2][4][4];
#pragma unroll
    for (int j = 0; j < 2; j++)
#pragma unroll
        for (int nt = 0; nt < 4; nt++)
#pragma unroll
            for (int u = 0; u < 4; u++)
                red[j][nt][u] = fmaxf(acc[j][nt][u], acc[j + 2][nt][u]);

    __syncthreads();
    if (wm == 1) {
#pragma unroll
        for (int j = 0; j < 2; j++)
#pragma unroll
            for (int nt = 0; nt < 4; nt++)
#pragma unroll
                for (int u = 0; u < 4; u++)
                    sbuf[wn * 1024 + ((j * 4 + nt) * 4 + u) * 32 + lane] =
                        red[j][nt][u];
    }
    __syncthreads();
    if (wm == 0) {
        int pe = p0 + lk * 2;
        float* Wb = g_W + (size_t)b * WSZ;
#pragma unroll
        for (int j = 0; j < 2; j++)
#pragma unroll
            for (int nt = 0; nt < 4; nt++) {
                float v0 = fmaxf(red[j][nt][0],
                                 sbuf[wn * 1024 + ((j * 4 + nt) * 4 + 0) * 32 + lane]);
                float v1 = fmaxf(red[j][nt][1],
                                 sbuf[wn * 1024 + ((j * 4 + nt) * 4 + 1) * 32 + lane]);
                float v2 = fmaxf(red[j][nt][2],
                                 sbuf[wn * 1024 + ((j * 4 + nt) * 4 + 2) * 32 + lane]);
                float v3 = fmaxf(red[j][nt][3],
                                 sbuf[wn * 1024 + ((j * 4 + nt) * 4 + 3) * 32 + lane]);
                if (pe < HW) {
                    int c  = c0 + wn * 4 + nt;
                    int s0 = (j * 16 + lr) * 128 + c;
                    *(float2*)(Wb + (size_t)s0 * HW + pe) = make_float2(v0, v1);
                    *(float2*)(Wb + (size_t)(s0 + 1024) * HW + pe) = make_float2(v2, v3);
                }
            }
    }
}

// ---------------- Kernel D: max over 49 strided rows (float4) --------------
__global__ void __launch_bounds__(256) maxred4(float* __restrict__ out) {
    int b = blockIdx.y;
    int m4 = blockIdx.x * 256 + threadIdx.x;   // float4 index
    const float4* Wb = (const float4*)(g_W + (size_t)b * WSZ);
    float4 a0 = make_float4(0.f, 0.f, 0.f, 0.f), a1 = a0, a2 = a0, a3 = a0;
#pragma unroll 3
    for (int j = 0; j < 48; j += 4) {
        float4 v0 = Wb[(size_t)(j + 0) * 4096 + m4];
        float4 v1 = Wb[(size_t)(j + 1) * 4096 + m4];
        float4 v2 = Wb[(size_t)(j + 2) * 4096 + m4];
        float4 v3 = Wb[(size_t)(j + 3) * 4096 + m4];
        a0.x = fmaxf(a0.x, v0.x); a0.y = fmaxf(a0.y, v0.y);
        a0.z = fmaxf(a0.z, v0.z); a0.w = fmaxf(a0.w, v0.w);
        a1.x = fmaxf(a1.x, v1.x); a1.y = fmaxf(a1.y, v1.y);
        a1.z = fmaxf(a1.z, v1.z); a1.w = fmaxf(a1.w, v1.w);
        a2.x = fmaxf(a2.x, v2.x); a2.y = fmaxf(a2.y, v2.y);
        a2.z = fmaxf(a2.z, v2.z); a2.w = fmaxf(a2.w, v2.w);
        a3.x = fmaxf(a3.x, v3.x); a3.y = fmaxf(a3.y, v3.y);
        a3.z = fmaxf(a3.z, v3.z); a3.w = fmaxf(a3.w, v3.w);
    }
    {
        float4 v = Wb[(size_t)48 * 4096 + m4];
        a0.x = fmaxf(a0.x, v.x); a0.y = fmaxf(a0.y, v.y);
        a0.z = fmaxf(a0.z, v.z); a0.w = fmaxf(a0.w, v.w);
    }
    float4 r;
    r.x = sqrtf(fmaxf(fmaxf(a0.x, a1.x), fmaxf(a2.x, a3.x)));
    r.y = sqrtf(fmaxf(fmaxf(a0.y, a1.y), fmaxf(a2.y, a3.y)));
    r.z = sqrtf(fmaxf(fmaxf(a0.z, a1.z), fmaxf(a2.z, a3.z)));
    r.w = sqrtf(fmaxf(fmaxf(a0.w, a1.w), fmaxf(a2.w, a3.w)));
    ((float4*)(out + b * MM))[m4] = r;

    float v = r.x * r.x + r.y * r.y + r.z * r.z + r.w * r.w;
#pragma unroll
    for (int off = 16; off; off >>= 1) v += __shfl_down_sync(0xffffffffu, v, off);
    __shared__ float ssum[8];
    if ((threadIdx.x & 31) == 0) ssum[threadIdx.x >> 5] = v;
    __syncthreads();
    if (threadIdx.x == 0) {
        float s = 0.f;
#pragma unroll
        for (int i = 0; i < 8; i++) s += ssum[i];
        g_part[b * 64 + blockIdx.x] = s;   // blocks 0..15 used; rest stay 0
    }
}

__global__ void normk() {
    __shared__ float s[64];
    int b = blockIdx.x, t = threadIdx.x;
    s[t] = g_part[b * 64 + t];
    __syncthreads();
#pragma unroll
    for (int st = 32; st; st >>= 1) {
        if (t < st) s[t] += s[t + st];
        __syncthreads();
    }
    if (t == 0) g_norm[b] = s[0] + EPSV;
}

__global__ void __launch_bounds__(256) divk(float* __restrict__ out) {
    int i = blockIdx.x * 256 + threadIdx.x;
    out[i] = out[i] / g_norm[i >> 14];
}

// ---------------- launch ----------------------------------------------------
extern "C" void kernel_launch(void* const* d_in, const int* in_sizes, int n_in,
                              void* d_out, int out_size) {
    const float* x = (const float*)d_in[0];
    const float* w = (const float*)d_in[1];
    if (in_sizes[0] == NC * CIN) { const float* t = x; x = w; w = t; }
    float* out = (float*)d_out;

    pw4<<<dim3(4, 4, NB * 4), 256>>>(x, w);
    prep<<<dim3(NC, NB), 256>>>();

    int smem = (128 * XRS + 2 * 16 * XDS + 16) * 2;   // 73760 bytes
    cudaFuncSetAttribute(corr6, cudaFuncAttributeMaxDynamicSharedMemorySize, smem);
    corr6<<<dim3(25, 8, NB), 256, smem>>>();

    maxred4<<<dim3(16, NB), 256>>>(out);
    normk<<<NB, 64>>>();
    divk<<<512, 256>>>(out);
}